// round 5
// baseline (speedup 1.0000x reference)
#include <cuda_runtime.h>
#include <cstdint>

#define NN 256   // nodes
#define FF 256   // feature dim
#define BB 32    // batch
#define EE 8192  // edges
#define CSR_CAP 12288    // EE + NN*7 = 9984 max padded entries, rounded up
#define SPAN_CAP 4096    // staged CSR entries per block (quarter-span worst case ~2800)

// Scratch (allocation-free): padded CSR of edges grouped by destination node.
// Row lengths padded to multiples of 8; pad entries are {src=0, w=0.0f}.
__device__ int g_row_ptr[NN + 1];
__device__ __align__(16) int2 g_csr[CSR_CAP];  // .x = src, .y = bits of cos(phase)/32

// ---------------------------------------------------------------------------
// Prep: detect index width (int32 vs int64 LE), build padded dst-CSR.
// ---------------------------------------------------------------------------
__global__ void ep_prep_kernel(const float* __restrict__ phase,
                               const int* __restrict__ src32,
                               const int* __restrict__ dst32) {
    __shared__ int s_cnt[NN];
    __shared__ int s_off[NN];
    __shared__ int s_is64;
    __shared__ int s_total;
    const int t = threadIdx.x;
    const int nt = blockDim.x;

    if (t == 0) {
        int ok = 1;
        for (int i = 0; i < 64; i++) {
            int lo = dst32[2 * i];
            int hi = dst32[2 * i + 1];
            if (hi != 0 || lo < 0 || lo >= NN) { ok = 0; break; }
        }
        s_is64 = ok;
    }
    for (int i = t; i < NN; i += nt) s_cnt[i] = 0;
    __syncthreads();
    const int is64 = s_is64;

    for (int e = t; e < EE; e += nt) {
        int d = is64 ? dst32[2 * e] : dst32[e];
        atomicAdd(&s_cnt[d], 1);
    }
    __syncthreads();

    if (t == 0) {
        int acc = 0;
        for (int i = 0; i < NN; i++) {
            g_row_ptr[i] = acc;
            s_off[i] = acc;
            acc += (s_cnt[i] + 7) & ~7;          // pad rows to multiple of 8
        }
        g_row_ptr[NN] = acc;
        s_total = acc;
    }
    __syncthreads();

    const int total = s_total;
    for (int i = t; i < total; i += nt) g_csr[i] = make_int2(0, 0);
    __syncthreads();

    for (int e = t; e < EE; e += nt) {
        int d = is64 ? dst32[2 * e] : dst32[e];
        int s = is64 ? src32[2 * e] : src32[e];
        int pos = atomicAdd(&s_off[d], 1);
        float c = cosf(phase[s * NN + d]) * (1.0f / 32.0f);
        g_csr[pos] = make_int2(s, __float_as_int(c));
    }
}

// ---------------------------------------------------------------------------
// Compute: block = (f-tile of 4 floats) x (quarter of the dst-node range).
// Grid 256 = 64 f-tiles x 4 node-quarters. SMEM: full x slice (128KB) + CSR
// span (<=32KB). One warp per dst node (lane = batch); 4 nodes per warp.
// Inner loop issues ALL 8 W gathers as a textual batch before any use ->
// real MLP=8 per warp, one latency exposure per 8 edges.
// ---------------------------------------------------------------------------
__global__ void __launch_bounds__(512, 1)
ep_compute_kernel(const float* __restrict__ x,   // [B, N, F]
                  const float* __restrict__ W,   // [N, N, F]
                  float* __restrict__ out) {     // [B, N, F]
    extern __shared__ char s_raw[];
    float4* s_x  = reinterpret_cast<float4*>(s_raw);                 // [NN*BB]
    int2* s_csr  = reinterpret_cast<int2*>(s_raw + NN * BB * 16);    // span
    __shared__ int s_rp[64 + 1];

    const int bx     = blockIdx.x;               // 0..255
    const int f0     = (bx >> 2) * 4;
    const int n_base = (bx & 3) * 64;
    const int t      = threadIdx.x;

    const int cbeg = g_row_ptr[n_base];
    const int cend = g_row_ptr[n_base + 64];
    const int span = cend - cbeg;

    // Stage CSR span (coalesced) and row pointers.
    if (span <= SPAN_CAP)
        for (int i = t; i < span; i += 512) s_csr[i] = g_csr[cbeg + i];
    for (int i = t; i < 64 + 1; i += 512) s_rp[i] = g_row_ptr[n_base + i];

    // Stage x tile: 8192 gathered float4s (x hits DRAM once per f-tile).
    for (int i = t; i < NN * BB; i += 512) {
        const int s = i >> 5;
        const int b = i & 31;
        s_x[i] = __ldg(reinterpret_cast<const float4*>(
            x + (size_t)(b * NN + s) * FF + f0));
    }
    __syncthreads();

    const int2* csr_base = (span <= SPAN_CAP) ? s_csr : (g_csr + cbeg);

    const int warp = t >> 5;   // 0..15
    const int lane = t & 31;   // batch index

    for (int k = 0; k < 4; k++) {
        const int nl  = warp + (k << 4);         // local dst index 0..63
        const int n   = n_base + nl;
        const int p   = s_rp[nl] - cbeg;         // multiple of 8 entries
        const int iters = (s_rp[nl + 1] - cbeg - p) >> 3;

        float4 a0 = make_float4(0.f, 0.f, 0.f, 0.f);
        float4 a1 = make_float4(0.f, 0.f, 0.f, 0.f);
        const float* Wn = W + (size_t)n * FF + f0;
        const int4* c4  = reinterpret_cast<const int4*>(csr_base + p);

        for (int it = 0; it < iters; it++) {
            // --- edge records (SMEM, cheap) ---
            const int4 q0 = c4[it * 4 + 0];
            const int4 q1 = c4[it * 4 + 1];
            const int4 q2 = c4[it * 4 + 2];
            const int4 q3 = c4[it * 4 + 3];
            // --- batch-issue all 8 W gathers (the latency-critical loads) ---
            const float4 w0 = __ldg(reinterpret_cast<const float4*>(Wn + (size_t)q0.x * (NN * FF)));
            const float4 w1 = __ldg(reinterpret_cast<const float4*>(Wn + (size_t)q0.z * (NN * FF)));
            const float4 w2 = __ldg(reinterpret_cast<const float4*>(Wn + (size_t)q1.x * (NN * FF)));
            const float4 w3 = __ldg(reinterpret_cast<const float4*>(Wn + (size_t)q1.z * (NN * FF)));
            const float4 w4 = __ldg(reinterpret_cast<const float4*>(Wn + (size_t)q2.x * (NN * FF)));
            const float4 w5 = __ldg(reinterpret_cast<const float4*>(Wn + (size_t)q2.z * (NN * FF)));
            const float4 w6 = __ldg(reinterpret_cast<const float4*>(Wn + (size_t)q3.x * (NN * FF)));
            const float4 w7 = __ldg(reinterpret_cast<const float4*>(Wn + (size_t)q3.z * (NN * FF)));
            // --- x reads from SMEM ---
            const float4 x0 = s_x[(q0.x << 5) + lane];
            const float4 x1 = s_x[(q0.z << 5) + lane];
            const float4 x2 = s_x[(q1.x << 5) + lane];
            const float4 x3 = s_x[(q1.z << 5) + lane];
            const float4 x4 = s_x[(q2.x << 5) + lane];
            const float4 x5 = s_x[(q2.z << 5) + lane];
            const float4 x6 = s_x[(q3.x << 5) + lane];
            const float4 x7 = s_x[(q3.z << 5) + lane];
            // --- math ---
            const float c0 = __int_as_float(q0.y), c1 = __int_as_float(q0.w);
            const float c2 = __int_as_float(q1.y), c3 = __int_as_float(q1.w);
            const float c4v = __int_as_float(q2.y), c5 = __int_as_float(q2.w);
            const float c6 = __int_as_float(q3.y), c7 = __int_as_float(q3.w);
            a0.x = fmaf(x0.x, w0.x * c0, a0.x); a0.y = fmaf(x0.y, w0.y * c0, a0.y);
            a0.z = fmaf(x0.z, w0.z * c0, a0.z); a0.w = fmaf(x0.w, w0.w * c0, a0.w);
            a1.x = fmaf(x1.x, w1.x * c1, a1.x); a1.y = fmaf(x1.y, w1.y * c1, a1.y);
            a1.z = fmaf(x1.z, w1.z * c1, a1.z); a1.w = fmaf(x1.w, w1.w * c1, a1.w);
            a0.x = fmaf(x2.x, w2.x * c2, a0.x); a0.y = fmaf(x2.y, w2.y * c2, a0.y);
            a0.z = fmaf(x2.z, w2.z * c2, a0.z); a0.w = fmaf(x2.w, w2.w * c2, a0.w);
            a1.x = fmaf(x3.x, w3.x * c3, a1.x); a1.y = fmaf(x3.y, w3.y * c3, a1.y);
            a1.z = fmaf(x3.z, w3.z * c3, a1.z); a1.w = fmaf(x3.w, w3.w * c3, a1.w);
            a0.x = fmaf(x4.x, w4.x * c4v, a0.x); a0.y = fmaf(x4.y, w4.y * c4v, a0.y);
            a0.z = fmaf(x4.z, w4.z * c4v, a0.z); a0.w = fmaf(x4.w, w4.w * c4v, a0.w);
            a1.x = fmaf(x5.x, w5.x * c5, a1.x); a1.y = fmaf(x5.y, w5.y * c5, a1.y);
            a1.z = fmaf(x5.z, w5.z * c5, a1.z); a1.w = fmaf(x5.w, w5.w * c5, a1.w);
            a0.x = fmaf(x6.x, w6.x * c6, a0.x); a0.y = fmaf(x6.y, w6.y * c6, a0.y);
            a0.z = fmaf(x6.z, w6.z * c6, a0.z); a0.w = fmaf(x6.w, w6.w * c6, a0.w);
            a1.x = fmaf(x7.x, w7.x * c7, a1.x); a1.y = fmaf(x7.y, w7.y * c7, a1.y);
            a1.z = fmaf(x7.z, w7.z * c7, a1.z); a1.w = fmaf(x7.w, w7.w * c7, a1.w);
        }

        float4 r = make_float4(a0.x + a1.x, a0.y + a1.y,
                               a0.z + a1.z, a0.w + a1.w);
        *reinterpret_cast<float4*>(out + (size_t)(lane * NN + n) * FF + f0) = r;
    }
}

// ---------------------------------------------------------------------------
extern "C" void kernel_launch(void* const* d_in, const int* in_sizes, int n_in,
                              void* d_out, int out_size) {
    const float* x     = (const float*)d_in[0];
    const float* W     = (const float*)d_in[1];
    const float* phase = (const float*)d_in[2];
    const int*   src   = (const int*)d_in[3];
    const int*   dst   = (const int*)d_in[4];
    float*       out   = (float*)d_out;

    // 128KB x-tile + 32KB CSR span = 163840 bytes (< 227KB limit).
    const int smem = NN * BB * 16 + SPAN_CAP * 8;
    cudaFuncSetAttribute(ep_compute_kernel,
                         cudaFuncAttributeMaxDynamicSharedMemorySize, smem);

    ep_prep_kernel<<<1, 512>>>(phase, src, dst);
    ep_compute_kernel<<<256, 512, smem>>>(x, W, out);
}

// round 6
// speedup vs baseline: 1.1532x; 1.1532x over previous
#include <cuda_runtime.h>
#include <cstdint>

#define NN 256   // nodes
#define FF 256   // feature dim
#define BB 32    // batch
#define EE 8192  // edges
#define CSR_CAP 12288    // EE + NN*7 = 9984 max padded entries, rounded up
#define SPAN_CAP 6144    // staged CSR entries per half-range block

// Scratch (allocation-free): padded CSR of edges grouped by destination node.
// Row lengths padded to multiples of 8; pad entries are {src=0, w=0.0f}.
__device__ int g_row_ptr[NN + 1];
__device__ __align__(16) int2 g_csr[CSR_CAP];  // .x = src, .y = bits of cos(phase)/32

// ---------------------------------------------------------------------------
// Prep: detect index width (int32 vs int64 LE), build padded dst-CSR.
// ---------------------------------------------------------------------------
__global__ void ep_prep_kernel(const float* __restrict__ phase,
                               const int* __restrict__ src32,
                               const int* __restrict__ dst32) {
    __shared__ int s_cnt[NN];
    __shared__ int s_off[NN];
    __shared__ int s_is64;
    __shared__ int s_total;
    const int t = threadIdx.x;
    const int nt = blockDim.x;

    if (t == 0) {
        int ok = 1;
        for (int i = 0; i < 64; i++) {
            int lo = dst32[2 * i];
            int hi = dst32[2 * i + 1];
            if (hi != 0 || lo < 0 || lo >= NN) { ok = 0; break; }
        }
        s_is64 = ok;
    }
    for (int i = t; i < NN; i += nt) s_cnt[i] = 0;
    __syncthreads();
    const int is64 = s_is64;

    for (int e = t; e < EE; e += nt) {
        int d = is64 ? dst32[2 * e] : dst32[e];
        atomicAdd(&s_cnt[d], 1);
    }
    __syncthreads();

    if (t == 0) {
        int acc = 0;
        for (int i = 0; i < NN; i++) {
            g_row_ptr[i] = acc;
            s_off[i] = acc;
            acc += (s_cnt[i] + 7) & ~7;          // pad rows to multiple of 8
        }
        g_row_ptr[NN] = acc;
        s_total = acc;
    }
    __syncthreads();

    const int total = s_total;
    for (int i = t; i < total; i += nt) g_csr[i] = make_int2(0, 0);
    __syncthreads();

    for (int e = t; e < EE; e += nt) {
        int d = is64 ? dst32[2 * e] : dst32[e];
        int s = is64 ? src32[2 * e] : src32[e];
        int pos = atomicAdd(&s_off[d], 1);
        float c = cosf(phase[s * NN + d]) * (1.0f / 32.0f);
        g_csr[pos] = make_int2(s, __float_as_int(c));
    }
}

// ---------------------------------------------------------------------------
// Compute: block = (f-tile of 4 floats) x (half of the dst-node range).
// Grid 128 = 64 f-tiles x 2 halves (1 wave). SMEM: full x slice (128KB) +
// CSR span (<=48KB) + per-warp edge staging buffers.
//
// One warp per dst node (lane = batch), 8 nodes per warp. Per node, the
// LOAD phase uses lane = edge: up to 64 edges fetched with just 2 divergent
// LDG.128s (all sectors in flight at once), each lane premultiplying its
// W float4 by cos/32 and staging {wc, src} in SMEM. The CONSUME phase walks
// staged edges with broadcast LDS (no global latency on the critical path).
// ---------------------------------------------------------------------------
__global__ void __launch_bounds__(512, 1)
ep_compute_kernel(const float* __restrict__ x,   // [B, N, F]
                  const float* __restrict__ W,   // [N, N, F]
                  float* __restrict__ out) {     // [B, N, F]
    extern __shared__ char s_raw[];
    float4* s_x  = reinterpret_cast<float4*>(s_raw);                 // [NN*BB]
    int2* s_csr  = reinterpret_cast<int2*>(s_raw + NN * BB * 16);    // span
    __shared__ float4 s_wc[16][64];   // staged W*c per warp
    __shared__ int    s_ss[16][64];   // staged src per warp
    __shared__ int    s_rp[128 + 1];

    const int bx     = blockIdx.x;               // 0..127
    const int f0     = (bx >> 1) * 4;
    const int n_base = (bx & 1) * 128;
    const int t      = threadIdx.x;

    const int cbeg = g_row_ptr[n_base];
    const int cend = g_row_ptr[n_base + 128];
    const int span = cend - cbeg;

    // Stage CSR span (coalesced) and row pointers.
    if (span <= SPAN_CAP)
        for (int i = t; i < span; i += 512) s_csr[i] = g_csr[cbeg + i];
    for (int i = t; i < 128 + 1; i += 512) s_rp[i] = g_row_ptr[n_base + i];

    // Stage x tile: 8192 gathered float4s (x hits DRAM once per f-tile).
    for (int i = t; i < NN * BB; i += 512) {
        const int s = i >> 5;
        const int b = i & 31;
        s_x[i] = __ldg(reinterpret_cast<const float4*>(
            x + (size_t)(b * NN + s) * FF + f0));
    }
    __syncthreads();

    const int2* csr = (span <= SPAN_CAP) ? s_csr : (g_csr + cbeg);

    const int warp = t >> 5;   // 0..15
    const int lane = t & 31;   // batch index (consume) / edge index (load)
    float4* wcbuf = s_wc[warp];
    int*    ssbuf = s_ss[warp];

    for (int k = 0; k < 8; k++) {
        const int nl = warp + (k << 4);          // local dst index 0..127
        const int n  = n_base + nl;
        const int p  = s_rp[nl] - cbeg;          // row start (mult of 8)
        const int pe = s_rp[nl + 1] - cbeg;      // row end   (mult of 8)

        float4 a0 = make_float4(0.f, 0.f, 0.f, 0.f);
        float4 a1 = make_float4(0.f, 0.f, 0.f, 0.f);
        const float* Wn = W + (size_t)n * FF + f0;

        for (int base = p; base < pe; base += 64) {
            // ---- LOAD phase: lane = edge; 2 divergent LDG.128 in flight ----
            const int i0 = base + lane;
            const int i1 = base + 32 + lane;
            const bool v0 = (i0 < pe);
            const bool v1 = (i1 < pe);
            int2 e0 = make_int2(0, 0), e1 = make_int2(0, 0);
            if (v0) e0 = csr[i0];
            if (v1) e1 = csr[i1];
            float4 w0 = make_float4(0.f, 0.f, 0.f, 0.f);
            float4 w1 = make_float4(0.f, 0.f, 0.f, 0.f);
            if (v0) w0 = __ldg(reinterpret_cast<const float4*>(
                          Wn + (size_t)e0.x * (NN * FF)));
            if (v1) w1 = __ldg(reinterpret_cast<const float4*>(
                          Wn + (size_t)e1.x * (NN * FF)));
            const float c0 = __int_as_float(e0.y);
            const float c1 = __int_as_float(e1.y);
            wcbuf[lane]      = make_float4(w0.x * c0, w0.y * c0,
                                           w0.z * c0, w0.w * c0);
            wcbuf[32 + lane] = make_float4(w1.x * c1, w1.y * c1,
                                           w1.z * c1, w1.w * c1);
            ssbuf[lane]      = e0.x;
            ssbuf[32 + lane] = e1.x;
            __syncwarp();

            // ---- CONSUME phase: lane = batch; broadcast LDS, 4 FMA/edge ----
            const int cnt = min(64, pe - base);  // multiple of 8
            for (int j = 0; j < cnt; j += 8) {
#pragma unroll
                for (int u = 0; u < 8; u++) {
                    const int    sv = ssbuf[j + u];
                    const float4 wc = wcbuf[j + u];
                    const float4 xv = s_x[(sv << 5) + lane];
                    if (u & 1) {
                        a1.x = fmaf(xv.x, wc.x, a1.x);
                        a1.y = fmaf(xv.y, wc.y, a1.y);
                        a1.z = fmaf(xv.z, wc.z, a1.z);
                        a1.w = fmaf(xv.w, wc.w, a1.w);
                    } else {
                        a0.x = fmaf(xv.x, wc.x, a0.x);
                        a0.y = fmaf(xv.y, wc.y, a0.y);
                        a0.z = fmaf(xv.z, wc.z, a0.z);
                        a0.w = fmaf(xv.w, wc.w, a0.w);
                    }
                }
            }
            __syncwarp();                        // before buffer reuse
        }

        float4 r = make_float4(a0.x + a1.x, a0.y + a1.y,
                               a0.z + a1.z, a0.w + a1.w);
        *reinterpret_cast<float4*>(out + (size_t)(lane * NN + n) * FF + f0) = r;
    }
}

// ---------------------------------------------------------------------------
extern "C" void kernel_launch(void* const* d_in, const int* in_sizes, int n_in,
                              void* d_out, int out_size) {
    const float* x     = (const float*)d_in[0];
    const float* W     = (const float*)d_in[1];
    const float* phase = (const float*)d_in[2];
    const int*   src   = (const int*)d_in[3];
    const int*   dst   = (const int*)d_in[4];
    float*       out   = (float*)d_out;

    // 128KB x-tile + 48KB CSR span (dynamic); ~21KB static staging buffers.
    const int smem = NN * BB * 16 + SPAN_CAP * 8;
    cudaFuncSetAttribute(ep_compute_kernel,
                         cudaFuncAttributeMaxDynamicSharedMemorySize, smem);

    ep_prep_kernel<<<1, 512>>>(phase, src, dst);
    ep_compute_kernel<<<128, 512, smem>>>(x, W, out);
}

// round 7
// speedup vs baseline: 1.3060x; 1.1326x over previous
#include <cuda_runtime.h>
#include <cuda_pipeline.h>
#include <cstdint>

#define NN 256   // nodes
#define FF 256   // feature dim
#define BB 32    // batch
#define EE 8192  // edges
#define CSR_CAP 12288    // EE + NN*7 = 9984 max padded entries, rounded up

// Scratch (allocation-free): padded CSR of edges grouped by destination node.
// Row lengths padded to multiples of 8; pad entries are {src=0, w=0.0f}.
__device__ int g_row_ptr[NN + 1];
__device__ __align__(16) int2 g_csr[CSR_CAP];  // .x = src, .y = bits of cos(phase)/32

// ---------------------------------------------------------------------------
// Prep: detect index width (int32 vs int64 LE), build padded dst-CSR.
// ---------------------------------------------------------------------------
__global__ void ep_prep_kernel(const float* __restrict__ phase,
                               const int* __restrict__ src32,
                               const int* __restrict__ dst32) {
    __shared__ int s_cnt[NN];
    __shared__ int s_off[NN];
    __shared__ int s_is64;
    __shared__ int s_total;
    const int t = threadIdx.x;
    const int nt = blockDim.x;

    if (t == 0) {
        int ok = 1;
        for (int i = 0; i < 64; i++) {
            int lo = dst32[2 * i];
            int hi = dst32[2 * i + 1];
            if (hi != 0 || lo < 0 || lo >= NN) { ok = 0; break; }
        }
        s_is64 = ok;
    }
    for (int i = t; i < NN; i += nt) s_cnt[i] = 0;
    __syncthreads();
    const int is64 = s_is64;

    for (int e = t; e < EE; e += nt) {
        int d = is64 ? dst32[2 * e] : dst32[e];
        atomicAdd(&s_cnt[d], 1);
    }
    __syncthreads();

    if (t == 0) {
        int acc = 0;
        for (int i = 0; i < NN; i++) {
            g_row_ptr[i] = acc;
            s_off[i] = acc;
            acc += (s_cnt[i] + 7) & ~7;          // pad rows to multiple of 8
        }
        g_row_ptr[NN] = acc;
        s_total = acc;
    }
    __syncthreads();

    const int total = s_total;
    for (int i = t; i < total; i += nt) g_csr[i] = make_int2(0, 0);
    __syncthreads();

    for (int e = t; e < EE; e += nt) {
        int d = is64 ? dst32[2 * e] : dst32[e];
        int s = is64 ? src32[2 * e] : src32[e];
        int pos = atomicAdd(&s_off[d], 1);
        float c = cosf(phase[s * NN + d]) * (1.0f / 32.0f);
        g_csr[pos] = make_int2(s, __float_as_int(c));
    }
}

// ---------------------------------------------------------------------------
// Compute: block = (f-tile of 4 floats) x (half of the dst-node range).
// Grid 128 = 64 f-tiles x 2 halves. 1024 threads = 32 warps/SM (occ 48%).
// SMEM: full x slice (128KB, via cp.async) + per-warp edge staging (40KB).
//
// One warp per dst node (lane = batch), 4 nodes per warp. Per node, the
// LOAD phase uses lane = edge: up to 64 edges fetched with 2 divergent
// LDG.128s (all sectors in flight), each lane premultiplying its W float4
// by cos/32 and staging {wc, src} in SMEM. The CONSUME phase walks staged
// edges with broadcast LDS — no global latency on the critical path.
// ---------------------------------------------------------------------------
__global__ void __launch_bounds__(1024, 1)
ep_compute_kernel(const float* __restrict__ x,   // [B, N, F]
                  const float* __restrict__ W,   // [N, N, F]
                  float* __restrict__ out) {     // [B, N, F]
    extern __shared__ char s_raw[];
    float4* s_x = reinterpret_cast<float4*>(s_raw);   // [NN*BB], idx = s*32+b
    __shared__ float4 s_wc[32][64];   // staged W*c per warp (32KB)
    __shared__ int    s_ss[32][64];   // staged src per warp (8KB)
    __shared__ int    s_rp[128 + 1];

    const int bx     = blockIdx.x;               // 0..127
    const int f0     = (bx >> 1) * 4;
    const int n_base = (bx & 1) * 128;
    const int t      = threadIdx.x;

    // Kick x-tile staging first (async, no register round-trip).
    for (int i = t; i < NN * BB; i += 1024) {
        const int s = i >> 5;
        const int b = i & 31;
        __pipeline_memcpy_async(&s_x[i],
                                x + (size_t)(b * NN + s) * FF + f0,
                                sizeof(float4));
    }
    __pipeline_commit();

    for (int i = t; i < 128 + 1; i += 1024) s_rp[i] = g_row_ptr[n_base + i];

    __pipeline_wait_prior(0);
    __syncthreads();

    const int warp = t >> 5;   // 0..31
    const int lane = t & 31;   // batch index (consume) / edge index (load)
    float4* wcbuf = s_wc[warp];
    int*    ssbuf = s_ss[warp];

    for (int k = 0; k < 4; k++) {
        const int nl = warp + (k << 5);          // local dst index 0..127
        const int n  = n_base + nl;
        const int p  = s_rp[nl];                 // absolute row start (mult 8)
        const int pe = s_rp[nl + 1];             // absolute row end

        float4 a0 = make_float4(0.f, 0.f, 0.f, 0.f);
        float4 a1 = make_float4(0.f, 0.f, 0.f, 0.f);
        const float* Wn = W + (size_t)n * FF + f0;

        for (int base = p; base < pe; base += 64) {
            // ---- LOAD phase: lane = edge; 2 divergent LDG.128 in flight ----
            const int i0 = base + lane;
            const int i1 = base + 32 + lane;
            const bool v0 = (i0 < pe);
            const bool v1 = (i1 < pe);
            int2 e0 = make_int2(0, 0), e1 = make_int2(0, 0);
            if (v0) e0 = g_csr[i0];
            if (v1) e1 = g_csr[i1];
            float4 w0 = make_float4(0.f, 0.f, 0.f, 0.f);
            float4 w1 = make_float4(0.f, 0.f, 0.f, 0.f);
            if (v0) w0 = __ldg(reinterpret_cast<const float4*>(
                          Wn + (size_t)e0.x * (NN * FF)));
            if (v1) w1 = __ldg(reinterpret_cast<const float4*>(
                          Wn + (size_t)e1.x * (NN * FF)));
            const float c0 = __int_as_float(e0.y);
            const float c1 = __int_as_float(e1.y);
            wcbuf[lane]      = make_float4(w0.x * c0, w0.y * c0,
                                           w0.z * c0, w0.w * c0);
            ssbuf[lane]      = e0.x;
            wcbuf[32 + lane] = make_float4(w1.x * c1, w1.y * c1,
                                           w1.z * c1, w1.w * c1);
            ssbuf[32 + lane] = e1.x;
            __syncwarp();

            // ---- CONSUME phase: lane = batch; broadcast LDS, 4 FMA/edge ----
            const int cnt = min(64, pe - base);  // multiple of 8
            for (int j = 0; j < cnt; j += 4) {
#pragma unroll
                for (int u = 0; u < 4; u++) {
                    const int    sv = ssbuf[j + u];
                    const float4 wc = wcbuf[j + u];
                    const float4 xv = s_x[(sv << 5) + lane];
                    if (u & 1) {
                        a1.x = fmaf(xv.x, wc.x, a1.x);
                        a1.y = fmaf(xv.y, wc.y, a1.y);
                        a1.z = fmaf(xv.z, wc.z, a1.z);
                        a1.w = fmaf(xv.w, wc.w, a1.w);
                    } else {
                        a0.x = fmaf(xv.x, wc.x, a0.x);
                        a0.y = fmaf(xv.y, wc.y, a0.y);
                        a0.z = fmaf(xv.z, wc.z, a0.z);
                        a0.w = fmaf(xv.w, wc.w, a0.w);
                    }
                }
            }
            __syncwarp();                        // before buffer reuse
        }

        float4 r = make_float4(a0.x + a1.x, a0.y + a1.y,
                               a0.z + a1.z, a0.w + a1.w);
        *reinterpret_cast<float4*>(out + (size_t)(lane * NN + n) * FF + f0) = r;
    }
}

// ---------------------------------------------------------------------------
extern "C" void kernel_launch(void* const* d_in, const int* in_sizes, int n_in,
                              void* d_out, int out_size) {
    const float* x     = (const float*)d_in[0];
    const float* W     = (const float*)d_in[1];
    const float* phase = (const float*)d_in[2];
    const int*   src   = (const int*)d_in[3];
    const int*   dst   = (const int*)d_in[4];
    float*       out   = (float*)d_out;

    const int smem = NN * BB * 16;   // 128KB dynamic x-tile
    cudaFuncSetAttribute(ep_compute_kernel,
                         cudaFuncAttributeMaxDynamicSharedMemorySize, smem);

    ep_prep_kernel<<<1, 512>>>(phase, src, dst);
    ep_compute_kernel<<<128, 1024, smem>>>(x, W, out);
}

// round 12
// speedup vs baseline: 1.6328x; 1.2502x over previous
#include <cuda_runtime.h>
#include <cuda_pipeline.h>
#include <cstdint>

#define NN 256   // nodes
#define FF 256   // feature dim
#define BB 32    // batch
#define EE 8192  // edges
#define SPAN_CAP 6144   // local CSR entries per half (actual ~4100 + pads)

// ---------------------------------------------------------------------------
// Single fused kernel. Block = (f-tile of 4 floats) x (half of dst range).
// Grid 128 = 64 f-tiles x 2 halves. 1024 threads (32 warps/SM, occ ~48%).
//
// Phase 0 (overlapped with x-tile cp.async): build this half's dst-CSR in
// SMEM — count, warp-scan (rows padded to 8), fill with SMEM atomics,
// weight = cos(phase)/32 premultiplied. Pad slots zeroed => no-op edges.
// Phase 1: one warp per dst node (lane = batch). LOAD: lane = edge, up to 64
// edges fetched with 2 divergent LDG.128s, premultiplied W*c staged in SMEM.
// CONSUME: lane = batch, broadcast LDS + conflict-free LDS.128 of x, 4 FMA
// per edge. No atomics in compute, no global CSR, single launch.
// ---------------------------------------------------------------------------
__global__ void __launch_bounds__(1024, 1)
ep_fused_kernel(const float* __restrict__ x,     // [B, N, F]
                const float* __restrict__ W,     // [N, N, F]
                const float* __restrict__ phase, // [N, N]
                const int* __restrict__ src32,
                const int* __restrict__ dst32,
                float* __restrict__ out) {       // [B, N, F]
    extern __shared__ char s_raw[];
    float4* s_x  = reinterpret_cast<float4*>(s_raw);               // 128KB
    int2*  s_csr = reinterpret_cast<int2*>(s_raw + NN * BB * 16);  // 48KB
    __shared__ float4 s_wc[32][64];   // staged W*c per warp (32KB)
    __shared__ int    s_ss[32][64];   // staged src per warp (8KB)
    __shared__ int    s_rp[128 + 1];
    __shared__ int    s_cnt[128];
    __shared__ int    s_off[128];
    __shared__ int    s_is64;

    const int bx     = blockIdx.x;               // 0..127
    const int f0     = (bx >> 1) * 4;
    const int n_base = (bx & 1) * 128;
    const int t      = threadIdx.x;
    const int warp   = t >> 5;
    const int lane   = t & 31;

    // ---- kick x-tile staging (async; overlaps the CSR build below) ----
    for (int i = t; i < NN * BB; i += 1024) {
        const int s = i >> 5;
        const int b = i & 31;
        __pipeline_memcpy_async(&s_x[i],
                                x + (size_t)(b * NN + s) * FF + f0,
                                sizeof(float4));
    }
    __pipeline_commit();

    // ---- detect index width (int32 vs int64 LE) ----
    if (t == 0) {
        int ok = 1;
        for (int i = 0; i < 64; i++) {
            int lo = dst32[2 * i];
            int hi = dst32[2 * i + 1];
            if (hi != 0 || lo < 0 || lo >= NN) { ok = 0; break; }
        }
        s_is64 = ok;
    }
    if (t < 128) s_cnt[t] = 0;
    __syncthreads();

    // stride-select instead of per-edge branch
    const int stride = s_is64 ? 2 : 1;

    // ---- count this half's rows ----
    for (int e = t; e < EE; e += 1024) {
        const int d = dst32[e * stride];
        const int nl = d - n_base;
        if ((unsigned)nl < 128u) atomicAdd(&s_cnt[nl], 1);
    }
    __syncthreads();

    // ---- warp 0: exclusive scan of 128 padded counts ----
    if (warp == 0) {
        const int i0 = lane * 4;
        const int c0 = (s_cnt[i0 + 0] + 7) & ~7;
        const int c1 = (s_cnt[i0 + 1] + 7) & ~7;
        const int c2 = (s_cnt[i0 + 2] + 7) & ~7;
        const int c3 = (s_cnt[i0 + 3] + 7) & ~7;
        const int tot = c0 + c1 + c2 + c3;
        int pre = tot;
        for (int off = 1; off < 32; off <<= 1) {
            const int v = __shfl_up_sync(0xFFFFFFFFu, pre, off);
            if (lane >= off) pre += v;
        }
        const int base = pre - tot;
        s_rp[i0 + 0] = base;
        s_rp[i0 + 1] = base + c0;
        s_rp[i0 + 2] = base + c0 + c1;
        s_rp[i0 + 3] = base + c0 + c1 + c2;
        if (lane == 31) s_rp[128] = base + tot;
    }
    __syncthreads();

    // ---- zero only the pad slots (tail of each padded row) ----
    if (t < 128) {
        s_off[t] = s_rp[t];
        const int fill_end = s_rp[t] + s_cnt[t];  // real entries end
        const int row_end  = s_rp[t + 1];         // padded row end
        for (int i = fill_end; i < row_end && i < SPAN_CAP; i++)
            s_csr[i] = make_int2(0, 0);
    }
    __syncthreads();

    // ---- fill: weight = cos(phase)/32 premultiplied ----
    for (int e = t; e < EE; e += 1024) {
        const int d = dst32[e * stride];
        const int nl = d - n_base;
        if ((unsigned)nl < 128u) {
            const int s = src32[e * stride];
            const int pos = atomicAdd(&s_off[nl], 1);
            if (pos < SPAN_CAP) {
                const float c = cosf(phase[s * NN + d]) * (1.0f / 32.0f);
                s_csr[pos] = make_int2(s, __float_as_int(c));
            }
        }
    }
    __pipeline_wait_prior(0);
    __syncthreads();

    // ---- phase 1: gather/scatter compute (proven R7 structure) ----
    float4* wcbuf = s_wc[warp];
    int*    ssbuf = s_ss[warp];

    for (int k = 0; k < 4; k++) {
        const int nl = warp + (k << 5);          // local dst index 0..127
        const int n  = n_base + nl;
        const int p  = s_rp[nl];                 // row start (mult of 8)
        const int pe = s_rp[nl + 1];             // row end

        float4 a0 = make_float4(0.f, 0.f, 0.f, 0.f);
        float4 a1 = make_float4(0.f, 0.f, 0.f, 0.f);
        const float* Wn = W + (size_t)n * FF + f0;

        for (int base = p; base < pe; base += 64) {
            // LOAD: lane = edge; 2 divergent LDG.128 in flight
            const int i0 = base + lane;
            const int i1 = base + 32 + lane;
            const bool v0 = (i0 < pe);
            const bool v1 = (i1 < pe);
            int2 e0 = make_int2(0, 0), e1 = make_int2(0, 0);
            if (v0) e0 = s_csr[i0];
            if (v1) e1 = s_csr[i1];
            float4 w0 = make_float4(0.f, 0.f, 0.f, 0.f);
            float4 w1 = make_float4(0.f, 0.f, 0.f, 0.f);
            if (v0) w0 = __ldg(reinterpret_cast<const float4*>(
                          Wn + (size_t)e0.x * (NN * FF)));
            if (v1) w1 = __ldg(reinterpret_cast<const float4*>(
                          Wn + (size_t)e1.x * (NN * FF)));
            const float c0 = __int_as_float(e0.y);
            const float c1 = __int_as_float(e1.y);
            wcbuf[lane]      = make_float4(w0.x * c0, w0.y * c0,
                                           w0.z * c0, w0.w * c0);
            ssbuf[lane]      = e0.x;
            wcbuf[32 + lane] = make_float4(w1.x * c1, w1.y * c1,
                                           w1.z * c1, w1.w * c1);
            ssbuf[32 + lane] = e1.x;
            __syncwarp();

            // CONSUME: lane = batch; broadcast LDS, 4 FMA/edge
            const int cnt = min(64, pe - base);  // multiple of 8
            for (int j = 0; j < cnt; j += 4) {
#pragma unroll
                for (int u = 0; u < 4; u++) {
                    const int    sv = ssbuf[j + u];
                    const float4 wc = wcbuf[j + u];
                    const float4 xv = s_x[(sv << 5) + lane];
                    if (u & 1) {
                        a1.x = fmaf(xv.x, wc.x, a1.x);
                        a1.y = fmaf(xv.y, wc.y, a1.y);
                        a1.z = fmaf(xv.z, wc.z, a1.z);
                        a1.w = fmaf(xv.w, wc.w, a1.w);
                    } else {
                        a0.x = fmaf(xv.x, wc.x, a0.x);
                        a0.y = fmaf(xv.y, wc.y, a0.y);
                        a0.z = fmaf(xv.z, wc.z, a0.z);
                        a0.w = fmaf(xv.w, wc.w, a0.w);
                    }
                }
            }
            __syncwarp();                        // before buffer reuse
        }

        float4 r = make_float4(a0.x + a1.x, a0.y + a1.y,
                               a0.z + a1.z, a0.w + a1.w);
        *reinterpret_cast<float4*>(out + (size_t)(lane * NN + n) * FF + f0) = r;
    }
}

// ---------------------------------------------------------------------------
extern "C" void kernel_launch(void* const* d_in, const int* in_sizes, int n_in,
                              void* d_out, int out_size) {
    const float* x     = (const float*)d_in[0];
    const float* W     = (const float*)d_in[1];
    const float* phase = (const float*)d_in[2];
    const int*   src   = (const int*)d_in[3];
    const int*   dst   = (const int*)d_in[4];
    float*       out   = (float*)d_out;

    // dynamic: 128KB x-tile + 48KB local CSR = 180224 B (static ~41KB).
    const int smem = NN * BB * 16 + SPAN_CAP * 8;
    cudaFuncSetAttribute(ep_fused_kernel,
                         cudaFuncAttributeMaxDynamicSharedMemorySize, smem);

    ep_fused_kernel<<<128, 1024, smem>>>(x, W, phase, src, dst, out);
}